// round 3
// baseline (speedup 1.0000x reference)
#include <cuda_runtime.h>
#include <math.h>
#include <stdint.h>

#define N_NODES 50000
#define N_EDGES 800000
#define NG      512
#define D       128
#define TXT     768
#define MAN     14
#define LN_EPS  1e-5f

// ---------------- scratch (device globals; no allocs allowed) ----------------
__device__ float g_h0 [N_NODES * D];   // layernorm(x)
__device__ float g_agg[N_NODES * D];   // neighbor sum -> (after GEMM input) mean
__device__ float g_deg[N_NODES];       // in-degree -> inverted in place
__device__ float g_h1 [N_NODES * D];   // GEMM out -> (in place) gelu(LN(.)) = h2
__device__ float g_gate[N_NODES];      // gate logits

__device__ __forceinline__ float gelu_exact(float x) {
    return 0.5f * x * (1.0f + erff(x * 0.70710678118654752440f));
}

// ---------------- K0: zero agg + deg ----------------
__global__ void k_zero() {
    int i = blockIdx.x * blockDim.x + threadIdx.x;
    if (i < (N_NODES * D) / 4) ((float4*)g_agg)[i] = make_float4(0.f, 0.f, 0.f, 0.f);
    if (i < N_NODES / 4)       ((float4*)g_deg)[i] = make_float4(0.f, 0.f, 0.f, 0.f);
}

// ---------------- K1: h0 = layernorm(x, w, b), warp per row ----------------
__global__ void k_ln_project(const float* __restrict__ x,
                             const float* __restrict__ w,
                             const float* __restrict__ b) {
    int warp = (blockIdx.x * blockDim.x + threadIdx.x) >> 5;
    int lane = threadIdx.x & 31;
    if (warp >= N_NODES) return;
    float4 v = ((const float4*)(x + (size_t)warp * D))[lane];
    float s = v.x + v.y + v.z + v.w;
    #pragma unroll
    for (int o = 16; o; o >>= 1) s += __shfl_xor_sync(0xffffffffu, s, o);
    float mu = s * (1.f / 128.f);
    float d0 = v.x - mu, d1 = v.y - mu, d2 = v.z - mu, d3 = v.w - mu;
    float q = d0 * d0 + d1 * d1 + d2 * d2 + d3 * d3;
    #pragma unroll
    for (int o = 16; o; o >>= 1) q += __shfl_xor_sync(0xffffffffu, q, o);
    float rstd = rsqrtf(q * (1.f / 128.f) + LN_EPS);
    float4 wv = ((const float4*)w)[lane];
    float4 bv = ((const float4*)b)[lane];
    float4 o4;
    o4.x = d0 * rstd * wv.x + bv.x;
    o4.y = d1 * rstd * wv.y + bv.y;
    o4.z = d2 * rstd * wv.z + bv.z;
    o4.w = d3 * rstd * wv.w + bv.w;
    ((float4*)(g_h0 + (size_t)warp * D))[lane] = o4;
}

// ---------------- K2: edge scatter (warp per edge) ----------------
__global__ void k_scatter(const int* __restrict__ ei) {
    int warp = (blockIdx.x * blockDim.x + threadIdx.x) >> 5;
    int lane = threadIdx.x & 31;
    if (warp >= N_EDGES) return;
    int src = 0, dst = 0;
    if (lane == 0) { src = ei[warp]; dst = ei[N_EDGES + warp]; }
    src = __shfl_sync(0xffffffffu, src, 0);
    dst = __shfl_sync(0xffffffffu, dst, 0);
    float4 v = ((const float4*)(g_h0 + (size_t)src * D))[lane];
    float* a = g_agg + (size_t)dst * D + lane * 4;
    atomicAdd(a + 0, v.x);
    atomicAdd(a + 1, v.y);
    atomicAdd(a + 2, v.z);
    atomicAdd(a + 3, v.w);
    if (lane == 0) atomicAdd(&g_deg[dst], 1.f);
}

// ---------------- K2b: deg -> 1/max(deg,1) ----------------
__global__ void k_invdeg() {
    int i = blockIdx.x * blockDim.x + threadIdx.x;
    if (i < N_NODES) g_deg[i] = 1.f / fmaxf(g_deg[i], 1.f);
}

// ---------------- K3: h1 = [mean_nb | h0] @ [Wl ; Wr] + bl ----------------
// tiled fp32 GEMM: BM=64 rows, BN=128 (full), BK=32, 256 threads, 4x8 per thread
#define BM 64
#define BK 32
__global__ void __launch_bounds__(256) k_sage_gemm(const float* __restrict__ Wl,
                                                   const float* __restrict__ Wr,
                                                   const float* __restrict__ bl) {
    __shared__ float As[BM][BK + 1];
    __shared__ float Ws[BK][D];
    int row0 = blockIdx.x * BM;
    int tid = threadIdx.x;
    int tx = tid & 15, ty = tid >> 4;
    float acc[4][8];
    #pragma unroll
    for (int r = 0; r < 4; r++)
        #pragma unroll
        for (int j = 0; j < 8; j++) acc[r][j] = 0.f;

    for (int k0 = 0; k0 < 2 * D; k0 += BK) {
        // load A tile (mean_nb for k<128 else h0)
        #pragma unroll
        for (int i = 0; i < 8; i++) {
            int e = tid + i * 256;
            int r = e >> 5, kk = e & 31;
            int row = row0 + r;
            float v = 0.f;
            if (row < N_NODES) {
                int kg = k0 + kk;
                if (kg < D) v = g_agg[(size_t)row * D + kg] * g_deg[row];
                else        v = g_h0 [(size_t)row * D + (kg - D)];
            }
            As[r][kk] = v;
        }
        // load W tile
        #pragma unroll
        for (int i = 0; i < 4; i++) {
            int e = tid + i * 256;      // float4 index within 32x128 tile
            int kk = e >> 5, c4 = e & 31;
            int kg = k0 + kk;
            const float* srcp = (kg < D) ? (Wl + (size_t)kg * D + c4 * 4)
                                         : (Wr + (size_t)(kg - D) * D + c4 * 4);
            *(float4*)&Ws[kk][c4 * 4] = *(const float4*)srcp;
        }
        __syncthreads();
        #pragma unroll
        for (int kk = 0; kk < BK; kk++) {
            float a0 = As[ty * 4 + 0][kk];
            float a1 = As[ty * 4 + 1][kk];
            float a2 = As[ty * 4 + 2][kk];
            float a3 = As[ty * 4 + 3][kk];
            float4 b0 = *(float4*)&Ws[kk][tx * 8];
            float4 b1 = *(float4*)&Ws[kk][tx * 8 + 4];
            float bb[8] = {b0.x, b0.y, b0.z, b0.w, b1.x, b1.y, b1.z, b1.w};
            #pragma unroll
            for (int j = 0; j < 8; j++) {
                acc[0][j] += a0 * bb[j];
                acc[1][j] += a1 * bb[j];
                acc[2][j] += a2 * bb[j];
                acc[3][j] += a3 * bb[j];
            }
        }
        __syncthreads();
    }
    #pragma unroll
    for (int r = 0; r < 4; r++) {
        int row = row0 + ty * 4 + r;
        if (row < N_NODES) {
            #pragma unroll
            for (int j = 0; j < 8; j++)
                g_h1[(size_t)row * D + tx * 8 + j] = acc[r][j] + bl[tx * 8 + j];
        }
    }
}

// ---------------- K4: h2 = gelu(LN(h1)) in place; gate = h2@gate_w + gate_b ----------------
__global__ void k_ln_gelu_gate(const float* __restrict__ w,
                               const float* __restrict__ b,
                               const float* __restrict__ gate_w,
                               const float* __restrict__ gate_b) {
    int warp = (blockIdx.x * blockDim.x + threadIdx.x) >> 5;
    int lane = threadIdx.x & 31;
    if (warp >= N_NODES) return;
    float4 v = ((const float4*)(g_h1 + (size_t)warp * D))[lane];
    float s = v.x + v.y + v.z + v.w;
    #pragma unroll
    for (int o = 16; o; o >>= 1) s += __shfl_xor_sync(0xffffffffu, s, o);
    float mu = s * (1.f / 128.f);
    float d0 = v.x - mu, d1 = v.y - mu, d2 = v.z - mu, d3 = v.w - mu;
    float q = d0 * d0 + d1 * d1 + d2 * d2 + d3 * d3;
    #pragma unroll
    for (int o = 16; o; o >>= 1) q += __shfl_xor_sync(0xffffffffu, q, o);
    float rstd = rsqrtf(q * (1.f / 128.f) + LN_EPS);
    float4 wv = ((const float4*)w)[lane];
    float4 bv = ((const float4*)b)[lane];
    float h0v = gelu_exact(d0 * rstd * wv.x + bv.x);
    float h1v = gelu_exact(d1 * rstd * wv.y + bv.y);
    float h2v = gelu_exact(d2 * rstd * wv.z + bv.z);
    float h3v = gelu_exact(d3 * rstd * wv.w + bv.w);
    float4 o4 = {h0v, h1v, h2v, h3v};
    ((float4*)(g_h1 + (size_t)warp * D))[lane] = o4;
    float4 gw = ((const float4*)gate_w)[lane];
    float p = h0v * gw.x + h1v * gw.y + h2v * gw.z + h3v * gw.w;
    #pragma unroll
    for (int o = 16; o; o >>= 1) p += __shfl_xor_sync(0xffffffffu, p, o);
    if (lane == 0) g_gate[warp] = p + gate_b[0];
}

// ---------------- K5: per-graph scatter-softmax + weighted pool ----------------
__device__ __forceinline__ int lower_bound_i(const int* a, int n, int v) {
    int lo = 0, hi = n;
    while (lo < hi) { int m = (lo + hi) >> 1; if (a[m] < v) lo = m + 1; else hi = m; }
    return lo;
}

__global__ void __launch_bounds__(128) k_attn_pool(const int* __restrict__ batch,
                                                   float* __restrict__ attn_out,
                                                   float* __restrict__ gemb) {
    __shared__ float red[128];
    __shared__ int s_lo, s_hi;
    int g = blockIdx.x, t = threadIdx.x;
    if (t == 0) {
        s_lo = lower_bound_i(batch, N_NODES, g);
        s_hi = lower_bound_i(batch, N_NODES, g + 1);
    }
    __syncthreads();
    int lo = s_lo, hi = s_hi;

    float m = -INFINITY;
    for (int i = lo + t; i < hi; i += 128) m = fmaxf(m, g_gate[i]);
    red[t] = m; __syncthreads();
    #pragma unroll
    for (int s = 64; s; s >>= 1) { if (t < s) red[t] = fmaxf(red[t], red[t + s]); __syncthreads(); }
    m = red[0]; __syncthreads();

    float sum = 0.f;
    for (int i = lo + t; i < hi; i += 128) sum += expf(g_gate[i] - m);
    red[t] = sum; __syncthreads();
    #pragma unroll
    for (int s = 64; s; s >>= 1) { if (t < s) red[t] += red[t + s]; __syncthreads(); }
    float denom = red[0]; __syncthreads();
    float inv = (denom > 0.f) ? 1.f / denom : 0.f;

    for (int i = lo + t; i < hi; i += 128) attn_out[i] = expf(g_gate[i] - m) * inv;
    __syncthreads();   // make attn writes visible block-wide

    float acc = 0.f;
    for (int i = lo; i < hi; i++) acc += attn_out[i] * g_h1[(size_t)i * D + t];
    gemb[g * D + t] = acc;
}

// ---------------- K6: head (msg GEMV, feat GEMV, LN-384, logits) ----------------
__global__ void __launch_bounds__(128) k_head(const float* __restrict__ text,
                                              const float* __restrict__ featm,
                                              const float* __restrict__ msgW,
                                              const float* __restrict__ msgb,
                                              const float* __restrict__ featW,
                                              const float* __restrict__ featb,
                                              const float* __restrict__ mw,
                                              const float* __restrict__ mb,
                                              const float* __restrict__ fcW,
                                              const float* __restrict__ fcb,
                                              const float* __restrict__ gws,
                                              const float* __restrict__ gemb,
                                              float* __restrict__ logits) {
    __shared__ float red[128];
    int g = blockIdx.x, t = threadIdx.x;

    const float* tr = text + (size_t)g * TXT;
    float accm = 0.f;
    #pragma unroll 4
    for (int k = 0; k < TXT; k++) accm += tr[k] * msgW[(size_t)k * D + t];
    accm = gelu_exact(accm + msgb[t]);

    const float* fr = featm + (size_t)g * MAN;
    float accf = 0.f;
    #pragma unroll
    for (int k = 0; k < MAN; k++) accf += fr[k] * featW[(size_t)k * D + t];
    accf = gelu_exact(accf + featb[t]);

    float e0 = gws[0] * gemb[(size_t)g * D + t];

    // LN over the concatenated 384-vector: each thread owns (e0, accm, accf)
    float s = e0 + accm + accf;
    red[t] = s; __syncthreads();
    #pragma unroll
    for (int ss = 64; ss; ss >>= 1) { if (t < ss) red[t] += red[t + ss]; __syncthreads(); }
    float mu = red[0] * (1.f / 384.f); __syncthreads();

    float d0 = e0 - mu, d1 = accm - mu, d2 = accf - mu;
    float q = d0 * d0 + d1 * d1 + d2 * d2;
    red[t] = q; __syncthreads();
    #pragma unroll
    for (int ss = 64; ss; ss >>= 1) { if (t < ss) red[t] += red[t + ss]; __syncthreads(); }
    float rstd = rsqrtf(red[0] * (1.f / 384.f) + LN_EPS); __syncthreads();

    float n0 = d0 * rstd * mw[t]       + mb[t];
    float n1 = d1 * rstd * mw[D + t]   + mb[D + t];
    float n2 = d2 * rstd * mw[2*D + t] + mb[2*D + t];
    float p = n0 * fcW[t] + n1 * fcW[D + t] + n2 * fcW[2*D + t];
    red[t] = p; __syncthreads();
    #pragma unroll
    for (int ss = 64; ss; ss >>= 1) { if (t < ss) red[t] += red[t + ss]; __syncthreads(); }
    if (t == 0) logits[g] = red[0] + fcb[0];
}

// ---------------- launch ----------------
extern "C" void kernel_launch(void* const* d_in, const int* in_sizes, int n_in,
                              void* d_out, int out_size) {
    (void)n_in; (void)out_size;
    const float* x          = (const float*)d_in[0];
    const int*   edge_index = (const int*)  d_in[1];
    const int*   batch      = (const int*)  d_in[2];
    // slot 3 may be the scalar batch_size; detect by element count
    int o = (in_sizes[3] == 1) ? 1 : 0;
    const float* text     = (const float*)d_in[3 + o];
    const float* featm    = (const float*)d_in[4 + o];
    const float* ln_pw    = (const float*)d_in[5 + o];
    const float* ln_pb    = (const float*)d_in[6 + o];
    const float* W_l      = (const float*)d_in[7 + o];
    const float* b_l      = (const float*)d_in[8 + o];
    const float* W_r      = (const float*)d_in[9 + o];
    const float* ln_cw    = (const float*)d_in[10 + o];
    const float* ln_cb    = (const float*)d_in[11 + o];
    const float* gate_w   = (const float*)d_in[12 + o];
    const float* gate_b   = (const float*)d_in[13 + o];
    const float* gweight  = (const float*)d_in[14 + o];
    const float* msg_W    = (const float*)d_in[15 + o];
    const float* msg_b    = (const float*)d_in[16 + o];
    const float* feat_W   = (const float*)d_in[17 + o];
    const float* feat_b   = (const float*)d_in[18 + o];
    const float* mixed_w  = (const float*)d_in[19 + o];
    const float* mixed_b  = (const float*)d_in[20 + o];
    const float* fc1_W    = (const float*)d_in[21 + o];
    const float* fc1_b    = (const float*)d_in[22 + o];

    float* out     = (float*)d_out;
    float* logits  = out;                 // [512]
    float* gemb    = out + NG;            // [512,128]
    float* attn    = out + NG + NG * D;   // [50000]

    k_zero<<<(N_NODES * D / 4 + 255) / 256, 256>>>();
    k_ln_project<<<(N_NODES + 7) / 8, 256>>>(x, ln_pw, ln_pb);
    k_scatter<<<(N_EDGES + 7) / 8, 256>>>(edge_index);
    k_invdeg<<<(N_NODES + 255) / 256, 256>>>();
    k_sage_gemm<<<(N_NODES + BM - 1) / BM, 256>>>(W_l, W_r, b_l);
    k_ln_gelu_gate<<<(N_NODES + 7) / 8, 256>>>(ln_cw, ln_cb, gate_w, gate_b);
    k_attn_pool<<<NG, 128>>>(batch, attn, gemb);
    k_head<<<NG, 128>>>(text, featm, msg_W, msg_b, feat_W, feat_b,
                        mixed_w, mixed_b, fc1_W, fc1_b, gweight, gemb, logits);
}

// round 4
// speedup vs baseline: 1.6766x; 1.6766x over previous
#include <cuda_runtime.h>
#include <math.h>
#include <stdint.h>

#define N_NODES 50000
#define N_EDGES 800000
#define NG      512
#define D       128
#define TXT     768
#define MAN     14
#define LN_EPS  1e-5f

// ---------------- scratch (device globals; no allocs allowed) ----------------
__device__ float g_h0 [N_NODES * D];   // layernorm(x)
__device__ float g_agg[N_NODES * D];   // neighbor sum
__device__ float g_deg[N_NODES];       // in-degree -> inverted in place
__device__ float g_h1 [N_NODES * D];   // GEMM out -> (in place) gelu(LN(.)) = h2
__device__ float g_gate[N_NODES];      // gate logits

__device__ __forceinline__ float gelu_exact(float x) {
    return 0.5f * x * (1.0f + erff(x * 0.70710678118654752440f));
}

// vectorized fp32 reduction (sm_90+): one LTS atomic op for 4 floats
__device__ __forceinline__ void red_add_v4(float* addr, float4 v) {
    unsigned long long ga;
    asm volatile("cvta.to.global.u64 %0, %1;" : "=l"(ga) : "l"(addr));
    asm volatile("red.global.add.v4.f32 [%0], {%1, %2, %3, %4};"
                 :: "l"(ga), "f"(v.x), "f"(v.y), "f"(v.z), "f"(v.w) : "memory");
}

// ---------------- K0: zero agg + deg ----------------
__global__ void k_zero() {
    int i = blockIdx.x * blockDim.x + threadIdx.x;
    if (i < (N_NODES * D) / 4) ((float4*)g_agg)[i] = make_float4(0.f, 0.f, 0.f, 0.f);
    if (i < N_NODES / 4)       ((float4*)g_deg)[i] = make_float4(0.f, 0.f, 0.f, 0.f);
}

// ---------------- K1: h0 = layernorm(x, w, b), warp per row ----------------
__global__ void k_ln_project(const float* __restrict__ x,
                             const float* __restrict__ w,
                             const float* __restrict__ b) {
    int warp = (blockIdx.x * blockDim.x + threadIdx.x) >> 5;
    int lane = threadIdx.x & 31;
    if (warp >= N_NODES) return;
    float4 v = ((const float4*)(x + (size_t)warp * D))[lane];
    float s = v.x + v.y + v.z + v.w;
    #pragma unroll
    for (int o = 16; o; o >>= 1) s += __shfl_xor_sync(0xffffffffu, s, o);
    float mu = s * (1.f / 128.f);
    float d0 = v.x - mu, d1 = v.y - mu, d2 = v.z - mu, d3 = v.w - mu;
    float q = d0 * d0 + d1 * d1 + d2 * d2 + d3 * d3;
    #pragma unroll
    for (int o = 16; o; o >>= 1) q += __shfl_xor_sync(0xffffffffu, q, o);
    float rstd = rsqrtf(q * (1.f / 128.f) + LN_EPS);
    float4 wv = ((const float4*)w)[lane];
    float4 bv = ((const float4*)b)[lane];
    float4 o4;
    o4.x = d0 * rstd * wv.x + bv.x;
    o4.y = d1 * rstd * wv.y + bv.y;
    o4.z = d2 * rstd * wv.z + bv.z;
    o4.w = d3 * rstd * wv.w + bv.w;
    ((float4*)(g_h0 + (size_t)warp * D))[lane] = o4;
}

// ---------------- K2: edge scatter (warp per edge, v4 reductions) ----------------
__global__ void k_scatter(const int* __restrict__ ei) {
    int warp = (blockIdx.x * blockDim.x + threadIdx.x) >> 5;
    int lane = threadIdx.x & 31;
    if (warp >= N_EDGES) return;
    int src = 0, dst = 0;
    if (lane == 0) { src = ei[warp]; dst = ei[N_EDGES + warp]; }
    src = __shfl_sync(0xffffffffu, src, 0);
    dst = __shfl_sync(0xffffffffu, dst, 0);
    float4 v = ((const float4*)(g_h0 + (size_t)src * D))[lane];
    red_add_v4(g_agg + (size_t)dst * D + lane * 4, v);
    if (lane == 0) atomicAdd(&g_deg[dst], 1.f);
}

// ---------------- K2b: deg -> 1/max(deg,1) ----------------
__global__ void k_invdeg() {
    int i = blockIdx.x * blockDim.x + threadIdx.x;
    if (i < N_NODES) g_deg[i] = 1.f / fmaxf(g_deg[i], 1.f);
}

// ---------------- K3: h1 = [mean_nb | h0] @ [Wl ; Wr] + bl ----------------
// BM=128 rows, BN=128 (full width), BK=16, 256 threads, 8x8 per thread
#define GBM 128
#define GBK 16
__global__ void __launch_bounds__(256) k_sage_gemm(const float* __restrict__ Wl,
                                                   const float* __restrict__ Wr,
                                                   const float* __restrict__ bl) {
    __shared__ float As[GBK][GBM];   // [k][m]
    __shared__ float Bs[GBK][D];     // [k][n]
    int row0 = blockIdx.x * GBM;
    int tid = threadIdx.x;
    int tx = tid & 15, ty = tid >> 4;          // n-tile, m-tile
    int m0 = ty * 8, n0 = tx * 8;

    // A-load mapping: thread -> (row r, 8 consecutive k)
    int ar  = tid >> 1;                        // 0..127
    int ak0 = (tid & 1) * 8;                   // 0 or 8
    int arow = row0 + ar;
    bool arow_ok = (arow < N_NODES);
    float inv = arow_ok ? g_deg[arow] : 0.f;

    // B-load mapping: thread -> 2 float4 of the 16x128 tile
    int b4a = tid * 2;                         // float4 idx 0..511
    int bk0 = b4a >> 5, bn0 = (b4a & 31) * 4;
    int bk1 = (b4a + 1) >> 5, bn1 = ((b4a + 1) & 31) * 4;

    float acc[8][8];
    #pragma unroll
    for (int i = 0; i < 8; i++)
        #pragma unroll
        for (int j = 0; j < 8; j++) acc[i][j] = 0.f;

    for (int k0 = 0; k0 < 2 * D; k0 += GBK) {
        // ---- load A tile (mean_nb for k<128 else h0), transpose to [k][m]
        {
            int kg = k0 + ak0;
            float4 v0, v1;
            if (arow_ok) {
                if (kg < D) {
                    const float4* p = (const float4*)(g_agg + (size_t)arow * D + kg);
                    v0 = p[0]; v1 = p[1];
                    v0.x *= inv; v0.y *= inv; v0.z *= inv; v0.w *= inv;
                    v1.x *= inv; v1.y *= inv; v1.z *= inv; v1.w *= inv;
                } else {
                    const float4* p = (const float4*)(g_h0 + (size_t)arow * D + (kg - D));
                    v0 = p[0]; v1 = p[1];
                }
            } else {
                v0 = make_float4(0.f, 0.f, 0.f, 0.f); v1 = v0;
            }
            As[ak0 + 0][ar] = v0.x; As[ak0 + 1][ar] = v0.y;
            As[ak0 + 2][ar] = v0.z; As[ak0 + 3][ar] = v0.w;
            As[ak0 + 4][ar] = v1.x; As[ak0 + 5][ar] = v1.y;
            As[ak0 + 6][ar] = v1.z; As[ak0 + 7][ar] = v1.w;
        }
        // ---- load B tile
        {
            int kg0 = k0 + bk0;
            const float* s0 = (kg0 < D) ? (Wl + (size_t)kg0 * D + bn0)
                                        : (Wr + (size_t)(kg0 - D) * D + bn0);
            *(float4*)&Bs[bk0][bn0] = *(const float4*)s0;
            int kg1 = k0 + bk1;
            const float* s1 = (kg1 < D) ? (Wl + (size_t)kg1 * D + bn1)
                                        : (Wr + (size_t)(kg1 - D) * D + bn1);
            *(float4*)&Bs[bk1][bn1] = *(const float4*)s1;
        }
        __syncthreads();
        #pragma unroll
        for (int kk = 0; kk < GBK; kk++) {
            float4 a0 = *(float4*)&As[kk][m0];
            float4 a1 = *(float4*)&As[kk][m0 + 4];
            float4 b0 = *(float4*)&Bs[kk][n0];
            float4 b1 = *(float4*)&Bs[kk][n0 + 4];
            float av[8] = {a0.x, a0.y, a0.z, a0.w, a1.x, a1.y, a1.z, a1.w};
            float bv[8] = {b0.x, b0.y, b0.z, b0.w, b1.x, b1.y, b1.z, b1.w};
            #pragma unroll
            for (int i = 0; i < 8; i++)
                #pragma unroll
                for (int j = 0; j < 8; j++)
                    acc[i][j] += av[i] * bv[j];
        }
        __syncthreads();
    }
    float bb[8];
    #pragma unroll
    for (int j = 0; j < 8; j++) bb[j] = bl[n0 + j];
    #pragma unroll
    for (int i = 0; i < 8; i++) {
        int row = row0 + m0 + i;
        if (row < N_NODES) {
            float4 o0 = {acc[i][0] + bb[0], acc[i][1] + bb[1], acc[i][2] + bb[2], acc[i][3] + bb[3]};
            float4 o1 = {acc[i][4] + bb[4], acc[i][5] + bb[5], acc[i][6] + bb[6], acc[i][7] + bb[7]};
            float4* dst = (float4*)(g_h1 + (size_t)row * D + n0);
            dst[0] = o0; dst[1] = o1;
        }
    }
}

// ---------------- K4: h2 = gelu(LN(h1)) in place; gate = h2@gate_w + gate_b ----------------
__global__ void k_ln_gelu_gate(const float* __restrict__ w,
                               const float* __restrict__ b,
                               const float* __restrict__ gate_w,
                               const float* __restrict__ gate_b) {
    int warp = (blockIdx.x * blockDim.x + threadIdx.x) >> 5;
    int lane = threadIdx.x & 31;
    if (warp >= N_NODES) return;
    float4 v = ((const float4*)(g_h1 + (size_t)warp * D))[lane];
    float s = v.x + v.y + v.z + v.w;
    #pragma unroll
    for (int o = 16; o; o >>= 1) s += __shfl_xor_sync(0xffffffffu, s, o);
    float mu = s * (1.f / 128.f);
    float d0 = v.x - mu, d1 = v.y - mu, d2 = v.z - mu, d3 = v.w - mu;
    float q = d0 * d0 + d1 * d1 + d2 * d2 + d3 * d3;
    #pragma unroll
    for (int o = 16; o; o >>= 1) q += __shfl_xor_sync(0xffffffffu, q, o);
    float rstd = rsqrtf(q * (1.f / 128.f) + LN_EPS);
    float4 wv = ((const float4*)w)[lane];
    float4 bv = ((const float4*)b)[lane];
    float h0v = gelu_exact(d0 * rstd * wv.x + bv.x);
    float h1v = gelu_exact(d1 * rstd * wv.y + bv.y);
    float h2v = gelu_exact(d2 * rstd * wv.z + bv.z);
    float h3v = gelu_exact(d3 * rstd * wv.w + bv.w);
    float4 o4 = {h0v, h1v, h2v, h3v};
    ((float4*)(g_h1 + (size_t)warp * D))[lane] = o4;
    float4 gw = ((const float4*)gate_w)[lane];
    float p = h0v * gw.x + h1v * gw.y + h2v * gw.z + h3v * gw.w;
    #pragma unroll
    for (int o = 16; o; o >>= 1) p += __shfl_xor_sync(0xffffffffu, p, o);
    if (lane == 0) g_gate[warp] = p + gate_b[0];
}

// ---------------- K5: per-graph scatter-softmax + weighted pool ----------------
__device__ __forceinline__ int lower_bound_i(const int* a, int n, int v) {
    int lo = 0, hi = n;
    while (lo < hi) { int m = (lo + hi) >> 1; if (a[m] < v) lo = m + 1; else hi = m; }
    return lo;
}

__global__ void __launch_bounds__(128) k_attn_pool(const int* __restrict__ batch,
                                                   float* __restrict__ attn_out,
                                                   float* __restrict__ gemb) {
    __shared__ float red[128];
    __shared__ int s_lo, s_hi;
    int g = blockIdx.x, t = threadIdx.x;
    if (t == 0) {
        s_lo = lower_bound_i(batch, N_NODES, g);
        s_hi = lower_bound_i(batch, N_NODES, g + 1);
    }
    __syncthreads();
    int lo = s_lo, hi = s_hi;

    float m = -INFINITY;
    for (int i = lo + t; i < hi; i += 128) m = fmaxf(m, g_gate[i]);
    red[t] = m; __syncthreads();
    #pragma unroll
    for (int s = 64; s; s >>= 1) { if (t < s) red[t] = fmaxf(red[t], red[t + s]); __syncthreads(); }
    m = red[0]; __syncthreads();

    float sum = 0.f;
    for (int i = lo + t; i < hi; i += 128) sum += expf(g_gate[i] - m);
    red[t] = sum; __syncthreads();
    #pragma unroll
    for (int s = 64; s; s >>= 1) { if (t < s) red[t] += red[t + s]; __syncthreads(); }
    float denom = red[0]; __syncthreads();
    float inv = (denom > 0.f) ? 1.f / denom : 0.f;

    for (int i = lo + t; i < hi; i += 128) attn_out[i] = expf(g_gate[i] - m) * inv;
    __syncthreads();

    float acc = 0.f;
    for (int i = lo; i < hi; i++) acc += attn_out[i] * g_h1[(size_t)i * D + t];
    gemb[g * D + t] = acc;
}

// ---------------- K6: head (msg GEMV, feat GEMV, LN-384, logits) ----------------
__global__ void __launch_bounds__(128) k_head(const float* __restrict__ text,
                                              const float* __restrict__ featm,
                                              const float* __restrict__ msgW,
                                              const float* __restrict__ msgb,
                                              const float* __restrict__ featW,
                                              const float* __restrict__ featb,
                                              const float* __restrict__ mw,
                                              const float* __restrict__ mb,
                                              const float* __restrict__ fcW,
                                              const float* __restrict__ fcb,
                                              const float* __restrict__ gws,
                                              const float* __restrict__ gemb,
                                              float* __restrict__ logits) {
    __shared__ float red[128];
    int g = blockIdx.x, t = threadIdx.x;

    const float* tr = text + (size_t)g * TXT;
    float accm = 0.f;
    #pragma unroll 4
    for (int k = 0; k < TXT; k++) accm += tr[k] * msgW[(size_t)k * D + t];
    accm = gelu_exact(accm + msgb[t]);

    const float* fr = featm + (size_t)g * MAN;
    float accf = 0.f;
    #pragma unroll
    for (int k = 0; k < MAN; k++) accf += fr[k] * featW[(size_t)k * D + t];
    accf = gelu_exact(accf + featb[t]);

    float e0 = gws[0] * gemb[(size_t)g * D + t];

    float s = e0 + accm + accf;
    red[t] = s; __syncthreads();
    #pragma unroll
    for (int ss = 64; ss; ss >>= 1) { if (t < ss) red[t] += red[t + ss]; __syncthreads(); }
    float mu = red[0] * (1.f / 384.f); __syncthreads();

    float d0 = e0 - mu, d1 = accm - mu, d2 = accf - mu;
    float q = d0 * d0 + d1 * d1 + d2 * d2;
    red[t] = q; __syncthreads();
    #pragma unroll
    for (int ss = 64; ss; ss >>= 1) { if (t < ss) red[t] += red[t + ss]; __syncthreads(); }
    float rstd = rsqrtf(red[0] * (1.f / 384.f) + LN_EPS); __syncthreads();

    float n0 = d0 * rstd * mw[t]       + mb[t];
    float n1 = d1 * rstd * mw[D + t]   + mb[D + t];
    float n2 = d2 * rstd * mw[2*D + t] + mb[2*D + t];
    float p = n0 * fcW[t] + n1 * fcW[D + t] + n2 * fcW[2*D + t];
    red[t] = p; __syncthreads();
    #pragma unroll
    for (int ss = 64; ss; ss >>= 1) { if (t < ss) red[t] += red[t + ss]; __syncthreads(); }
    if (t == 0) logits[g] = red[0] + fcb[0];
}

// ---------------- launch ----------------
extern "C" void kernel_launch(void* const* d_in, const int* in_sizes, int n_in,
                              void* d_out, int out_size) {
    (void)n_in; (void)out_size;
    const float* x          = (const float*)d_in[0];
    const int*   edge_index = (const int*)  d_in[1];
    const int*   batch      = (const int*)  d_in[2];
    int o = (in_sizes[3] == 1) ? 1 : 0;   // skip scalar batch_size slot if present
    const float* text     = (const float*)d_in[3 + o];
    const float* featm    = (const float*)d_in[4 + o];
    const float* ln_pw    = (const float*)d_in[5 + o];
    const float* ln_pb    = (const float*)d_in[6 + o];
    const float* W_l      = (const float*)d_in[7 + o];
    const float* b_l      = (const float*)d_in[8 + o];
    const float* W_r      = (const float*)d_in[9 + o];
    const float* ln_cw    = (const float*)d_in[10 + o];
    const float* ln_cb    = (const float*)d_in[11 + o];
    const float* gate_w   = (const float*)d_in[12 + o];
    const float* gate_b   = (const float*)d_in[13 + o];
    const float* gweight  = (const float*)d_in[14 + o];
    const float* msg_W    = (const float*)d_in[15 + o];
    const float* msg_b    = (const float*)d_in[16 + o];
    const float* feat_W   = (const float*)d_in[17 + o];
    const float* feat_b   = (const float*)d_in[18 + o];
    const float* mixed_w  = (const float*)d_in[19 + o];
    const float* mixed_b  = (const float*)d_in[20 + o];
    const float* fc1_W    = (const float*)d_in[21 + o];
    const float* fc1_b    = (const float*)d_in[22 + o];

    float* out     = (float*)d_out;
    float* logits  = out;                 // [512]
    float* gemb    = out + NG;            // [512,128]
    float* attn    = out + NG + NG * D;   // [50000]

    k_zero<<<(N_NODES * D / 4 + 255) / 256, 256>>>();
    k_ln_project<<<(N_NODES + 7) / 8, 256>>>(x, ln_pw, ln_pb);
    k_scatter<<<(N_EDGES + 7) / 8, 256>>>(edge_index);
    k_invdeg<<<(N_NODES + 255) / 256, 256>>>();
    k_sage_gemm<<<(N_NODES + GBM - 1) / GBM, 256>>>(W_l, W_r, b_l);
    k_ln_gelu_gate<<<(N_NODES + 7) / 8, 256>>>(ln_cw, ln_cb, gate_w, gate_b);
    k_attn_pool<<<NG, 128>>>(batch, attn, gemb);
    k_head<<<NG, 128>>>(text, featm, msg_W, msg_b, feat_W, feat_b,
                        mixed_w, mixed_b, fc1_W, fc1_b, gweight, gemb, logits);
}

// round 5
// speedup vs baseline: 1.9042x; 1.1358x over previous
#include <cuda_runtime.h>
#include <math.h>
#include <stdint.h>

#define N_NODES 50000
#define N_EDGES 800000
#define NG      512
#define D       128
#define TXT     768
#define MAN     14
#define LN_EPS  1e-5f

// ---------------- scratch (device globals; no allocs allowed) ----------------
__device__ float g_h0 [N_NODES * D];   // layernorm(x)
__device__ float g_agg[N_NODES * D];   // neighbor sum
__device__ float g_deg[N_NODES];       // in-degree
__device__ float g_h1 [N_NODES * D];   // h2 = gelu(LN(GEMM out))
__device__ float g_gate[N_NODES];      // gate logits

__device__ __forceinline__ float gelu_exact(float x) {
    return 0.5f * x * (1.0f + erff(x * 0.70710678118654752440f));
}

__device__ __forceinline__ void red_add_v4(float* addr, float4 v) {
    unsigned long long ga;
    asm volatile("cvta.to.global.u64 %0, %1;" : "=l"(ga) : "l"(addr));
    asm volatile("red.global.add.v4.f32 [%0], {%1, %2, %3, %4};"
                 :: "l"(ga), "f"(v.x), "f"(v.y), "f"(v.z), "f"(v.w) : "memory");
}

__device__ __forceinline__ unsigned tf32_of(float x) {
    unsigned u;
    asm("cvt.rna.tf32.f32 %0, %1;" : "=r"(u) : "f"(x));
    return u;
}

#define MMA_TF32(c, a, b)                                                     \
    asm volatile("mma.sync.aligned.m16n8k8.row.col.f32.tf32.tf32.f32 "        \
                 "{%0,%1,%2,%3}, {%4,%5,%6,%7}, {%8,%9}, {%0,%1,%2,%3};"      \
                 : "+f"((c)[0]), "+f"((c)[1]), "+f"((c)[2]), "+f"((c)[3])     \
                 : "r"((a)[0]), "r"((a)[1]), "r"((a)[2]), "r"((a)[3]),        \
                   "r"((b)[0]), "r"((b)[1]))

// ---------------- K1: h0 = layernorm(x); also zero g_agg row + g_deg ----------------
__global__ void k_ln_project(const float* __restrict__ x,
                             const float* __restrict__ w,
                             const float* __restrict__ b) {
    int warp = (blockIdx.x * blockDim.x + threadIdx.x) >> 5;
    int lane = threadIdx.x & 31;
    if (warp >= N_NODES) return;
    float4 v = ((const float4*)(x + (size_t)warp * D))[lane];
    float s = v.x + v.y + v.z + v.w;
    #pragma unroll
    for (int o = 16; o; o >>= 1) s += __shfl_xor_sync(0xffffffffu, s, o);
    float mu = s * (1.f / 128.f);
    float d0 = v.x - mu, d1 = v.y - mu, d2 = v.z - mu, d3 = v.w - mu;
    float q = d0 * d0 + d1 * d1 + d2 * d2 + d3 * d3;
    #pragma unroll
    for (int o = 16; o; o >>= 1) q += __shfl_xor_sync(0xffffffffu, q, o);
    float rstd = rsqrtf(q * (1.f / 128.f) + LN_EPS);
    float4 wv = ((const float4*)w)[lane];
    float4 bv = ((const float4*)b)[lane];
    float4 o4;
    o4.x = d0 * rstd * wv.x + bv.x;
    o4.y = d1 * rstd * wv.y + bv.y;
    o4.z = d2 * rstd * wv.z + bv.z;
    o4.w = d3 * rstd * wv.w + bv.w;
    ((float4*)(g_h0 + (size_t)warp * D))[lane] = o4;
    // fused zeroing for the scatter phase
    ((float4*)(g_agg + (size_t)warp * D))[lane] = make_float4(0.f, 0.f, 0.f, 0.f);
    if (lane == 0) g_deg[warp] = 0.f;
}

// ---------------- K2: edge scatter (warp per edge, v4 reductions) ----------------
__global__ void k_scatter(const int* __restrict__ ei) {
    int warp = (blockIdx.x * blockDim.x + threadIdx.x) >> 5;
    int lane = threadIdx.x & 31;
    if (warp >= N_EDGES) return;
    int src = 0, dst = 0;
    if (lane == 0) { src = ei[warp]; dst = ei[N_EDGES + warp]; }
    src = __shfl_sync(0xffffffffu, src, 0);
    dst = __shfl_sync(0xffffffffu, dst, 0);
    float4 v = ((const float4*)(g_h0 + (size_t)src * D))[lane];
    red_add_v4(g_agg + (size_t)dst * D + lane * 4, v);
    if (lane == 0) atomicAdd(&g_deg[dst], 1.f);
}

// ---------------- K3: fused 3xTF32 GEMM + LN + GELU + gate ----------------
// h1 = [mean_nb | h0] @ [Wl ; Wr] + bl, then h2 = gelu(LN(h1)), gate = h2.gw+gb
// block = 128 rows x 128 cols, 256 threads, 8 warps (4 m x 2 n), warp = 32x64
#define GBM 128
// smem float offsets
#define OFF_AHI 0
#define OFF_ALO (128 * 36)
#define OFF_BHI (2 * 128 * 36)
#define OFF_BLO (2 * 128 * 36 + 32 * 136)
#define SM_FLOATS (2 * 128 * 36 + 2 * 32 * 136)   // 17920 floats = 71680 B

__global__ void __launch_bounds__(256, 1) k_gemm_fused(
        const float* __restrict__ Wl, const float* __restrict__ Wr,
        const float* __restrict__ bl,
        const float* __restrict__ lnw, const float* __restrict__ lnb,
        const float* __restrict__ gate_w, const float* __restrict__ gate_b) {
    extern __shared__ float sm[];
    float* As_hi = sm + OFF_AHI;   // [128][36]
    float* As_lo = sm + OFF_ALO;   // [128][36]
    float* Bs_hi = sm + OFF_BHI;   // [32][136]
    float* Bs_lo = sm + OFF_BLO;   // [32][136]
    float* Cs    = sm;             // [128][132] alias (after mainloop)

    const int tid  = threadIdx.x;
    const int lane = tid & 31, wid = tid >> 5;
    const int row0 = blockIdx.x * GBM;
    const int wm = wid >> 1, wn = wid & 1;
    const int g = lane >> 2, tig = lane & 3;

    // A loader mapping: thread -> (row, half of 8 float4s)
    const int arow = tid >> 1;
    const int akq  = (tid & 1) * 4;
    const int growA = row0 + arow;
    const bool aok = growA < N_NODES;
    const float inv = aok ? 1.f / fmaxf(g_deg[growA], 1.f) : 0.f;

    float c[2][8][4];
    #pragma unroll
    for (int mt = 0; mt < 2; mt++)
        #pragma unroll
        for (int nt = 0; nt < 8; nt++)
            #pragma unroll
            for (int j = 0; j < 4; j++) c[mt][nt][j] = 0.f;

    for (int k0 = 0; k0 < 2 * D; k0 += 32) {
        // ---- stage A tile (split hi/lo tf32)
        {
            const bool lhs = (k0 < D);
            const float scale = lhs ? inv : 1.f;
            const float* srcrow = lhs ? (g_agg + (size_t)growA * D + k0)
                                      : (g_h0  + (size_t)growA * D + (k0 - D));
            #pragma unroll
            for (int i = 0; i < 4; i++) {
                float4 v = aok ? ((const float4*)srcrow)[akq + i]
                               : make_float4(0.f, 0.f, 0.f, 0.f);
                v.x *= scale; v.y *= scale; v.z *= scale; v.w *= scale;
                int base = arow * 36 + (akq + i) * 4;
                float f[4] = {v.x, v.y, v.z, v.w};
                #pragma unroll
                for (int cmp = 0; cmp < 4; cmp++) {
                    unsigned hu = tf32_of(f[cmp]);
                    float hf = __uint_as_float(hu);
                    As_hi[base + cmp] = hf;
                    As_lo[base + cmp] = __uint_as_float(tf32_of(f[cmp] - hf));
                }
            }
        }
        // ---- stage B tile
        #pragma unroll
        for (int i = 0; i < 4; i++) {
            int e = tid + i * 256;                // 0..1023 float4 slots
            int bk = e >> 5, bn = (e & 31) * 4;
            int kg = k0 + bk;
            const float* srcp = (kg < D) ? (Wl + (size_t)kg * D + bn)
                                         : (Wr + (size_t)(kg - D) * D + bn);
            float4 v = *(const float4*)srcp;
            int base = bk * 136 + bn;
            float f[4] = {v.x, v.y, v.z, v.w};
            #pragma unroll
            for (int cmp = 0; cmp < 4; cmp++) {
                unsigned hu = tf32_of(f[cmp]);
                float hf = __uint_as_float(hu);
                Bs_hi[base + cmp] = hf;
                Bs_lo[base + cmp] = __uint_as_float(tf32_of(f[cmp] - hf));
            }
        }
        __syncthreads();
        // ---- 4 k-steps of 8
        #pragma unroll
        for (int ks = 0; ks < 32; ks += 8) {
            unsigned ah[2][4], al[2][4];
            #pragma unroll
            for (int mt = 0; mt < 2; mt++) {
                int r = wm * 32 + mt * 16 + g;
                int k = ks + tig;
                ah[mt][0] = __float_as_uint(As_hi[r * 36 + k]);
                ah[mt][1] = __float_as_uint(As_hi[(r + 8) * 36 + k]);
                ah[mt][2] = __float_as_uint(As_hi[r * 36 + k + 4]);
                ah[mt][3] = __float_as_uint(As_hi[(r + 8) * 36 + k + 4]);
                al[mt][0] = __float_as_uint(As_lo[r * 36 + k]);
                al[mt][1] = __float_as_uint(As_lo[(r + 8) * 36 + k]);
                al[mt][2] = __float_as_uint(As_lo[r * 36 + k + 4]);
                al[mt][3] = __float_as_uint(As_lo[(r + 8) * 36 + k + 4]);
            }
            unsigned bh[8][2], blo[8][2];
            #pragma unroll
            for (int nt = 0; nt < 8; nt++) {
                int n = wn * 64 + nt * 8 + g;
                bh[nt][0]  = __float_as_uint(Bs_hi[(ks + tig) * 136 + n]);
                bh[nt][1]  = __float_as_uint(Bs_hi[(ks + tig + 4) * 136 + n]);
                blo[nt][0] = __float_as_uint(Bs_lo[(ks + tig) * 136 + n]);
                blo[nt][1] = __float_as_uint(Bs_lo[(ks + tig + 4) * 136 + n]);
            }
            #pragma unroll
            for (int mt = 0; mt < 2; mt++)
                #pragma unroll
                for (int nt = 0; nt < 8; nt++) {
                    MMA_TF32(c[mt][nt], ah[mt], bh[nt]);
                    MMA_TF32(c[mt][nt], ah[mt], blo[nt]);
                    MMA_TF32(c[mt][nt], al[mt], bh[nt]);
                }
        }
        __syncthreads();
    }

    // ---- dump C to smem [128][132]
    #pragma unroll
    for (int mt = 0; mt < 2; mt++)
        #pragma unroll
        for (int nt = 0; nt < 8; nt++) {
            int r  = wm * 32 + mt * 16 + g;
            int cc = wn * 64 + nt * 8 + 2 * tig;
            Cs[r * 132 + cc]           = c[mt][nt][0];
            Cs[r * 132 + cc + 1]       = c[mt][nt][1];
            Cs[(r + 8) * 132 + cc]     = c[mt][nt][2];
            Cs[(r + 8) * 132 + cc + 1] = c[mt][nt][3];
        }
    __syncthreads();

    // ---- epilogue: bias + LN + gelu + gate, warp per row (16 rows/warp)
    float4 bl4 = ((const float4*)bl)[lane];
    float4 wv  = ((const float4*)lnw)[lane];
    float4 bv  = ((const float4*)lnb)[lane];
    float4 gw  = ((const float4*)gate_w)[lane];
    float gb = gate_b[0];
    #pragma unroll 1
    for (int i = 0; i < 16; i++) {
        int r = wid * 16 + i;
        int grow = row0 + r;
        if (grow >= N_NODES) break;
        float4 v = *(float4*)&Cs[r * 132 + lane * 4];
        v.x += bl4.x; v.y += bl4.y; v.z += bl4.z; v.w += bl4.w;
        float s = v.x + v.y + v.z + v.w;
        #pragma unroll
        for (int o = 16; o; o >>= 1) s += __shfl_xor_sync(0xffffffffu, s, o);
        float mu = s * (1.f / 128.f);
        float d0 = v.x - mu, d1 = v.y - mu, d2 = v.z - mu, d3 = v.w - mu;
        float q = d0 * d0 + d1 * d1 + d2 * d2 + d3 * d3;
        #pragma unroll
        for (int o = 16; o; o >>= 1) q += __shfl_xor_sync(0xffffffffu, q, o);
        float rstd = rsqrtf(q * (1.f / 128.f) + LN_EPS);
        float h0v = gelu_exact(d0 * rstd * wv.x + bv.x);
        float h1v = gelu_exact(d1 * rstd * wv.y + bv.y);
        float h2v = gelu_exact(d2 * rstd * wv.z + bv.z);
        float h3v = gelu_exact(d3 * rstd * wv.w + bv.w);
        float4 o4 = {h0v, h1v, h2v, h3v};
        ((float4*)(g_h1 + (size_t)grow * D))[lane] = o4;
        float p = h0v * gw.x + h1v * gw.y + h2v * gw.z + h3v * gw.w;
        #pragma unroll
        for (int o = 16; o; o >>= 1) p += __shfl_xor_sync(0xffffffffu, p, o);
        if (lane == 0) g_gate[grow] = p + gb;
    }
}

// ---------------- K5: per-graph scatter-softmax + weighted pool ----------------
__device__ __forceinline__ int lower_bound_i(const int* a, int n, int v) {
    int lo = 0, hi = n;
    while (lo < hi) { int m = (lo + hi) >> 1; if (a[m] < v) lo = m + 1; else hi = m; }
    return lo;
}

__global__ void __launch_bounds__(128) k_attn_pool(const int* __restrict__ batch,
                                                   float* __restrict__ attn_out,
                                                   float* __restrict__ gemb) {
    __shared__ float red[128];
    __shared__ int s_lo, s_hi;
    int gidx = blockIdx.x, t = threadIdx.x;
    if (t == 0) {
        s_lo = lower_bound_i(batch, N_NODES, gidx);
        s_hi = lower_bound_i(batch, N_NODES, gidx + 1);
    }
    __syncthreads();
    int lo = s_lo, hi = s_hi;

    float m = -INFINITY;
    for (int i = lo + t; i < hi; i += 128) m = fmaxf(m, g_gate[i]);
    red[t] = m; __syncthreads();
    #pragma unroll
    for (int s = 64; s; s >>= 1) { if (t < s) red[t] = fmaxf(red[t], red[t + s]); __syncthreads(); }
    m = red[0]; __syncthreads();

    float sum = 0.f;
    for (int i = lo + t; i < hi; i += 128) sum += expf(g_gate[i] - m);
    red[t] = sum; __syncthreads();
    #pragma unroll
    for (int s = 64; s; s >>= 1) { if (t < s) red[t] += red[t + s]; __syncthreads(); }
    float denom = red[0]; __syncthreads();
    float inv = (denom > 0.f) ? 1.f / denom : 0.f;

    for (int i = lo + t; i < hi; i += 128) attn_out[i] = expf(g_gate[i] - m) * inv;
    __syncthreads();

    float acc = 0.f;
    for (int i = lo; i < hi; i++) acc += attn_out[i] * g_h1[(size_t)i * D + t];
    gemb[gidx * D + t] = acc;
}

// ---------------- K6: head (msg GEMV, feat GEMV, LN-384, logits) ----------------
__global__ void __launch_bounds__(128) k_head(const float* __restrict__ text,
                                              const float* __restrict__ featm,
                                              const float* __restrict__ msgW,
                                              const float* __restrict__ msgb,
                                              const float* __restrict__ featW,
                                              const float* __restrict__ featb,
                                              const float* __restrict__ mw,
                                              const float* __restrict__ mb,
                                              const float* __restrict__ fcW,
                                              const float* __restrict__ fcb,
                                              const float* __restrict__ gws,
                                              const float* __restrict__ gemb,
                                              float* __restrict__ logits) {
    __shared__ float red[128];
    int gidx = blockIdx.x, t = threadIdx.x;

    const float* tr = text + (size_t)gidx * TXT;
    float accm = 0.f;
    #pragma unroll 4
    for (int k = 0; k < TXT; k++) accm += tr[k] * msgW[(size_t)k * D + t];
    accm = gelu_exact(accm + msgb[t]);

    const float* fr = featm + (size_t)gidx * MAN;
    float accf = 0.f;
    #pragma unroll
    for (int k = 0; k < MAN; k++) accf += fr[k] * featW[(size_t)k * D + t];
    accf = gelu_exact(accf + featb[t]);

    float e0 = gws[0] * gemb[(size_t)gidx * D + t];

    float s = e0 + accm + accf;
    red[t] = s; __syncthreads();
    #pragma unroll
    for (int ss = 64; ss; ss >>= 1) { if (t < ss) red[t] += red[t + ss]; __syncthreads(); }
    float mu = red[0] * (1.f / 384.f); __syncthreads();

    float d0 = e0 - mu, d1 = accm - mu, d2 = accf - mu;
    float q = d0 * d0 + d1 * d1 + d2 * d2;
    red[t] = q; __syncthreads();
    #pragma unroll
    for (int ss = 64; ss; ss >>= 1) { if (t < ss) red[t] += red[t + ss]; __syncthreads(); }
    float rstd = rsqrtf(red[0] * (1.f / 384.f) + LN_EPS); __syncthreads();

    float n0 = d0 * rstd * mw[t]       + mb[t];
    float n1 = d1 * rstd * mw[D + t]   + mb[D + t];
    float n2 = d2 * rstd * mw[2*D + t] + mb[2*D + t];
    float p = n0 * fcW[t] + n1 * fcW[D + t] + n2 * fcW[2*D + t];
    red[t] = p; __syncthreads();
    #pragma unroll
    for (int ss = 64; ss; ss >>= 1) { if (t < ss) red[t] += red[t + ss]; __syncthreads(); }
    if (t == 0) logits[gidx] = red[0] + fcb[0];
}

// ---------------- launch ----------------
extern "C" void kernel_launch(void* const* d_in, const int* in_sizes, int n_in,
                              void* d_out, int out_size) {
    (void)n_in; (void)out_size;
    const float* x          = (const float*)d_in[0];
    const int*   edge_index = (const int*)  d_in[1];
    const int*   batch      = (const int*)  d_in[2];
    int o = (in_sizes[3] == 1) ? 1 : 0;   // skip scalar batch_size slot if present
    const float* text     = (const float*)d_in[3 + o];
    const float* featm    = (const float*)d_in[4 + o];
    const float* ln_pw    = (const float*)d_in[5 + o];
    const float* ln_pb    = (const float*)d_in[6 + o];
    const float* W_l      = (const float*)d_in[7 + o];
    const float* b_l      = (const float*)d_in[8 + o];
    const float* W_r      = (const float*)d_in[9 + o];
    const float* ln_cw    = (const float*)d_in[10 + o];
    const float* ln_cb    = (const float*)d_in[11 + o];
    const float* gate_w   = (const float*)d_in[12 + o];
    const float* gate_b   = (const float*)d_in[13 + o];
    const float* gweight  = (const float*)d_in[14 + o];
    const float* msg_W    = (const float*)d_in[15 + o];
    const float* msg_b    = (const float*)d_in[16 + o];
    const float* feat_W   = (const float*)d_in[17 + o];
    const float* feat_b   = (const float*)d_in[18 + o];
    const float* mixed_w  = (const float*)d_in[19 + o];
    const float* mixed_b  = (const float*)d_in[20 + o];
    const float* fc1_W    = (const float*)d_in[21 + o];
    const float* fc1_b    = (const float*)d_in[22 + o];

    float* out     = (float*)d_out;
    float* logits  = out;                 // [512]
    float* gemb    = out + NG;            // [512,128]
    float* attn    = out + NG + NG * D;   // [50000]

    static int smem_set = 0;
    (void)smem_set;
    cudaFuncSetAttribute(k_gemm_fused, cudaFuncAttributeMaxDynamicSharedMemorySize,
                         SM_FLOATS * (int)sizeof(float));

    k_ln_project<<<(N_NODES + 7) / 8, 256>>>(x, ln_pw, ln_pb);
    k_scatter<<<(N_EDGES + 7) / 8, 256>>>(edge_index);
    k_gemm_fused<<<(N_NODES + GBM - 1) / GBM, 256, SM_FLOATS * sizeof(float)>>>(
        W_l, W_r, b_l, ln_cw, ln_cb, gate_w, gate_b);
    k_attn_pool<<<NG, 128>>>(batch, attn, gemb);
    k_head<<<NG, 128>>>(text, featm, msg_W, msg_b, feat_W, feat_b,
                        mixed_w, mixed_b, fc1_W, fc1_b, gweight, gemb, logits);
}

// round 6
// speedup vs baseline: 2.1027x; 1.1042x over previous
#include <cuda_runtime.h>
#include <math.h>
#include <stdint.h>

#define N_NODES 50000
#define N_EDGES 800000
#define NG      512
#define D       128
#define TXT     768
#define MAN     14
#define LN_EPS  1e-5f
#define SCAN_BLOCKS 49   // ceil(50000/1024)

// ---------------- scratch (device globals; no allocs allowed) ----------------
__device__ float g_h0 [N_NODES * D];   // layernorm(x)
__device__ float g_agg[N_NODES * D];   // neighbor MEAN
__device__ float g_h1 [N_NODES * D];   // h2 = gelu(LN(GEMM out))
__device__ float g_gate[N_NODES];      // gate logits
__device__ int   g_cnt[N_NODES];       // in-degree histogram
__device__ int   g_off[N_NODES];       // exclusive scan (bucket start)
__device__ int   g_cursor[N_NODES];    // scatter cursor
__device__ int   g_part[64];           // scan partials
__device__ int   g_ssrc[N_EDGES];      // src sorted by dst

__device__ __forceinline__ float gelu_exact(float x) {
    return 0.5f * x * (1.0f + erff(x * 0.70710678118654752440f));
}

__device__ __forceinline__ unsigned tf32_of(float x) {
    unsigned u;
    asm("cvt.rna.tf32.f32 %0, %1;" : "=r"(u) : "f"(x));
    return u;
}

#define MMA_TF32(c, a, b)                                                     \
    asm volatile("mma.sync.aligned.m16n8k8.row.col.f32.tf32.tf32.f32 "        \
                 "{%0,%1,%2,%3}, {%4,%5,%6,%7}, {%8,%9}, {%0,%1,%2,%3};"      \
                 : "+f"((c)[0]), "+f"((c)[1]), "+f"((c)[2]), "+f"((c)[3])     \
                 : "r"((a)[0]), "r"((a)[1]), "r"((a)[2]), "r"((a)[3]),        \
                   "r"((b)[0]), "r"((b)[1]))

// ---------------- K1: h0 = layernorm(x); zero histogram ----------------
__global__ void k_ln_project(const float* __restrict__ x,
                             const float* __restrict__ w,
                             const float* __restrict__ b) {
    int warp = (blockIdx.x * blockDim.x + threadIdx.x) >> 5;
    int lane = threadIdx.x & 31;
    if (warp >= N_NODES) return;
    float4 v = ((const float4*)(x + (size_t)warp * D))[lane];
    float s = v.x + v.y + v.z + v.w;
    #pragma unroll
    for (int o = 16; o; o >>= 1) s += __shfl_xor_sync(0xffffffffu, s, o);
    float mu = s * (1.f / 128.f);
    float d0 = v.x - mu, d1 = v.y - mu, d2 = v.z - mu, d3 = v.w - mu;
    float q = d0 * d0 + d1 * d1 + d2 * d2 + d3 * d3;
    #pragma unroll
    for (int o = 16; o; o >>= 1) q += __shfl_xor_sync(0xffffffffu, q, o);
    float rstd = rsqrtf(q * (1.f / 128.f) + LN_EPS);
    float4 wv = ((const float4*)w)[lane];
    float4 bv = ((const float4*)b)[lane];
    float4 o4;
    o4.x = d0 * rstd * wv.x + bv.x;
    o4.y = d1 * rstd * wv.y + bv.y;
    o4.z = d2 * rstd * wv.z + bv.z;
    o4.w = d3 * rstd * wv.w + bv.w;
    ((float4*)(g_h0 + (size_t)warp * D))[lane] = o4;
    if (lane == 0) g_cnt[warp] = 0;
}

// ---------------- K2: histogram of dst ----------------
__global__ void k_hist(const int* __restrict__ ei) {
    int e = blockIdx.x * blockDim.x + threadIdx.x;
    if (e < N_EDGES) atomicAdd(&g_cnt[ei[N_EDGES + e]], 1);
}

// ---------------- K3a/b/c: exclusive scan of g_cnt -> g_off ----------------
__global__ void k_scanA() {
    __shared__ int s[1024];
    int t = threadIdx.x;
    int i = blockIdx.x * 1024 + t;
    int v = (i < N_NODES) ? g_cnt[i] : 0;
    s[t] = v; __syncthreads();
    #pragma unroll
    for (int off = 1; off < 1024; off <<= 1) {
        int a = (t >= off) ? s[t - off] : 0;
        __syncthreads();
        s[t] += a; __syncthreads();
    }
    if (i < N_NODES) g_off[i] = s[t] - v;   // exclusive within block
    if (t == 1023) g_part[blockIdx.x] = s[1023];
}
__global__ void k_scanB() {
    __shared__ int s[64];
    int t = threadIdx.x;
    if (t < SCAN_BLOCKS) s[t] = g_part[t];
    __syncthreads();
    if (t == 0) {
        int run = 0;
        for (int b = 0; b < SCAN_BLOCKS; b++) { int tmp = s[b]; s[b] = run; run += tmp; }
    }
    __syncthreads();
    if (t < SCAN_BLOCKS) g_part[t] = s[t];
}
__global__ void k_scanC() {
    int i = blockIdx.x * blockDim.x + threadIdx.x;
    if (i < N_NODES) {
        int o = g_off[i] + g_part[i >> 10];
        g_off[i] = o;
        g_cursor[i] = o;
    }
}

// ---------------- K4: scatter src into dst-sorted order ----------------
__global__ void k_edge_sort(const int* __restrict__ ei) {
    int e = blockIdx.x * blockDim.x + threadIdx.x;
    if (e >= N_EDGES) return;
    int src = ei[e];
    int dst = ei[N_EDGES + e];
    int pos = atomicAdd(&g_cursor[dst], 1);
    g_ssrc[pos] = src;
}

// ---------------- K5: per-node mean aggregation (warp per node, no atomics) ----------------
__global__ void __launch_bounds__(256) k_aggregate() {
    int warp = (blockIdx.x * blockDim.x + threadIdx.x) >> 5;
    int lane = threadIdx.x & 31;
    if (warp >= N_NODES) return;
    int start = g_off[warp];
    int cnt   = g_cnt[warp];
    float4 acc = make_float4(0.f, 0.f, 0.f, 0.f);
    for (int j0 = 0; j0 < cnt; j0 += 32) {
        int idx = (j0 + lane < cnt) ? g_ssrc[start + j0 + lane] : 0;
        int nb = min(32, cnt - j0);
        #pragma unroll 4
        for (int jj = 0; jj < nb; jj++) {
            int s = __shfl_sync(0xffffffffu, idx, jj);
            float4 v = ((const float4*)(g_h0 + (size_t)s * D))[lane];
            acc.x += v.x; acc.y += v.y; acc.z += v.z; acc.w += v.w;
        }
    }
    float inv = 1.f / fmaxf((float)cnt, 1.f);
    acc.x *= inv; acc.y *= inv; acc.z *= inv; acc.w *= inv;
    ((float4*)(g_agg + (size_t)warp * D))[lane] = acc;
}

// ---------------- K6: fused 3xTF32 GEMM + LN + GELU + gate ----------------
#define GBM 128
#define OFF_AHI 0
#define OFF_ALO (128 * 36)
#define OFF_BHI (2 * 128 * 36)
#define OFF_BLO (2 * 128 * 36 + 32 * 136)
#define SM_FLOATS (2 * 128 * 36 + 2 * 32 * 136)

__global__ void __launch_bounds__(256, 1) k_gemm_fused(
        const float* __restrict__ Wl, const float* __restrict__ Wr,
        const float* __restrict__ bl,
        const float* __restrict__ lnw, const float* __restrict__ lnb,
        const float* __restrict__ gate_w, const float* __restrict__ gate_b) {
    extern __shared__ float sm[];
    float* As_hi = sm + OFF_AHI;
    float* As_lo = sm + OFF_ALO;
    float* Bs_hi = sm + OFF_BHI;
    float* Bs_lo = sm + OFF_BLO;
    float* Cs    = sm;

    const int tid  = threadIdx.x;
    const int lane = tid & 31, wid = tid >> 5;
    const int row0 = blockIdx.x * GBM;
    const int wm = wid >> 1, wn = wid & 1;
    const int g = lane >> 2, tig = lane & 3;

    const int arow = tid >> 1;
    const int akq  = (tid & 1) * 4;
    const int growA = row0 + arow;
    const bool aok = growA < N_NODES;

    float c[2][8][4];
    #pragma unroll
    for (int mt = 0; mt < 2; mt++)
        #pragma unroll
        for (int nt = 0; nt < 8; nt++)
            #pragma unroll
            for (int j = 0; j < 4; j++) c[mt][nt][j] = 0.f;

    for (int k0 = 0; k0 < 2 * D; k0 += 32) {
        {
            const bool lhs = (k0 < D);
            const float* srcrow = lhs ? (g_agg + (size_t)growA * D + k0)
                                      : (g_h0  + (size_t)growA * D + (k0 - D));
            #pragma unroll
            for (int i = 0; i < 4; i++) {
                float4 v = aok ? ((const float4*)srcrow)[akq + i]
                               : make_float4(0.f, 0.f, 0.f, 0.f);
                int base = arow * 36 + (akq + i) * 4;
                float f[4] = {v.x, v.y, v.z, v.w};
                #pragma unroll
                for (int cmp = 0; cmp < 4; cmp++) {
                    unsigned hu = tf32_of(f[cmp]);
                    float hf = __uint_as_float(hu);
                    As_hi[base + cmp] = hf;
                    As_lo[base + cmp] = __uint_as_float(tf32_of(f[cmp] - hf));
                }
            }
        }
        #pragma unroll
        for (int i = 0; i < 4; i++) {
            int e = tid + i * 256;
            int bk = e >> 5, bn = (e & 31) * 4;
            int kg = k0 + bk;
            const float* srcp = (kg < D) ? (Wl + (size_t)kg * D + bn)
                                         : (Wr + (size_t)(kg - D) * D + bn);
            float4 v = *(const float4*)srcp;
            int base = bk * 136 + bn;
            float f[4] = {v.x, v.y, v.z, v.w};
            #pragma unroll
            for (int cmp = 0; cmp < 4; cmp++) {
                unsigned hu = tf32_of(f[cmp]);
                float hf = __uint_as_float(hu);
                Bs_hi[base + cmp] = hf;
                Bs_lo[base + cmp] = __uint_as_float(tf32_of(f[cmp] - hf));
            }
        }
        __syncthreads();
        #pragma unroll
        for (int ks = 0; ks < 32; ks += 8) {
            unsigned ah[2][4], al[2][4];
            #pragma unroll
            for (int mt = 0; mt < 2; mt++) {
                int r = wm * 32 + mt * 16 + g;
                int k = ks + tig;
                ah[mt][0] = __float_as_uint(As_hi[r * 36 + k]);
                ah[mt][1] = __float_as_uint(As_hi[(r + 8) * 36 + k]);
                ah[mt][2] = __float_as_uint(As_hi[r * 36 + k + 4]);
                ah[mt][3] = __float_as_uint(As_hi[(r + 8) * 36 + k + 4]);
                al[mt][0] = __float_as_uint(As_lo[r * 36 + k]);
                al[mt][1] = __float_as_uint(As_lo[(r + 8) * 36 + k]);
                al[mt][2] = __float_as_uint(As_lo[r * 36 + k + 4]);
                al[mt][3] = __float_as_uint(As_lo[(r + 8) * 36 + k + 4]);
            }
            unsigned bh[8][2], blo[8][2];
            #pragma unroll
            for (int nt = 0; nt < 8; nt++) {
                int n = wn * 64 + nt * 8 + g;
                bh[nt][0]  = __float_as_uint(Bs_hi[(ks + tig) * 136 + n]);
                bh[nt][1]  = __float_as_uint(Bs_hi[(ks + tig + 4) * 136 + n]);
                blo[nt][0] = __float_as_uint(Bs_lo[(ks + tig) * 136 + n]);
                blo[nt][1] = __float_as_uint(Bs_lo[(ks + tig + 4) * 136 + n]);
            }
            #pragma unroll
            for (int mt = 0; mt < 2; mt++)
                #pragma unroll
                for (int nt = 0; nt < 8; nt++) {
                    MMA_TF32(c[mt][nt], ah[mt], bh[nt]);
                    MMA_TF32(c[mt][nt], ah[mt], blo[nt]);
                    MMA_TF32(c[mt][nt], al[mt], bh[nt]);
                }
        }
        __syncthreads();
    }

    #pragma unroll
    for (int mt = 0; mt < 2; mt++)
        #pragma unroll
        for (int nt = 0; nt < 8; nt++) {
            int r  = wm * 32 + mt * 16 + g;
            int cc = wn * 64 + nt * 8 + 2 * tig;
            Cs[r * 132 + cc]           = c[mt][nt][0];
            Cs[r * 132 + cc + 1]       = c[mt][nt][1];
            Cs[(r + 8) * 132 + cc]     = c[mt][nt][2];
            Cs[(r + 8) * 132 + cc + 1] = c[mt][nt][3];
        }
    __syncthreads();

    float4 bl4 = ((const float4*)bl)[lane];
    float4 wv  = ((const float4*)lnw)[lane];
    float4 bv  = ((const float4*)lnb)[lane];
    float4 gw  = ((const float4*)gate_w)[lane];
    float gb = gate_b[0];
    #pragma unroll 1
    for (int i = 0; i < 16; i++) {
        int r = wid * 16 + i;
        int grow = row0 + r;
        if (grow >= N_NODES) break;
        float4 v = *(float4*)&Cs[r * 132 + lane * 4];
        v.x += bl4.x; v.y += bl4.y; v.z += bl4.z; v.w += bl4.w;
        float s = v.x + v.y + v.z + v.w;
        #pragma unroll
        for (int o = 16; o; o >>= 1) s += __shfl_xor_sync(0xffffffffu, s, o);
        float mu = s * (1.f / 128.f);
        float d0 = v.x - mu, d1 = v.y - mu, d2 = v.z - mu, d3 = v.w - mu;
        float q = d0 * d0 + d1 * d1 + d2 * d2 + d3 * d3;
        #pragma unroll
        for (int o = 16; o; o >>= 1) q += __shfl_xor_sync(0xffffffffu, q, o);
        float rstd = rsqrtf(q * (1.f / 128.f) + LN_EPS);
        float h0v = gelu_exact(d0 * rstd * wv.x + bv.x);
        float h1v = gelu_exact(d1 * rstd * wv.y + bv.y);
        float h2v = gelu_exact(d2 * rstd * wv.z + bv.z);
        float h3v = gelu_exact(d3 * rstd * wv.w + bv.w);
        float4 o4 = {h0v, h1v, h2v, h3v};
        ((float4*)(g_h1 + (size_t)grow * D))[lane] = o4;
        float p = h0v * gw.x + h1v * gw.y + h2v * gw.z + h3v * gw.w;
        #pragma unroll
        for (int o = 16; o; o >>= 1) p += __shfl_xor_sync(0xffffffffu, p, o);
        if (lane == 0) g_gate[grow] = p + gb;
    }
}

// ---------------- K7: per-graph scatter-softmax + weighted pool ----------------
__device__ __forceinline__ int lower_bound_i(const int* a, int n, int v) {
    int lo = 0, hi = n;
    while (lo < hi) { int m = (lo + hi) >> 1; if (a[m] < v) lo = m + 1; else hi = m; }
    return lo;
}

__global__ void __launch_bounds__(128) k_attn_pool(const int* __restrict__ batch,
                                                   float* __restrict__ attn_out,
                                                   float* __restrict__ gemb) {
    __shared__ float red[128];
    __shared__ int s_lo, s_hi;
    int gidx = blockIdx.x, t = threadIdx.x;
    if (t == 0) {
        s_lo = lower_bound_i(batch, N_NODES, gidx);
        s_hi = lower_bound_i(batch, N_NODES, gidx + 1);
    }
    __syncthreads();
    int lo = s_lo, hi = s_hi;

    float m = -INFINITY;
    for (int i = lo + t; i < hi; i += 128) m = fmaxf(m, g_gate[i]);
    red[t] = m; __syncthreads();
    #pragma unroll
    for (int s = 64; s; s >>= 1) { if (t < s) red[t] = fmaxf(red[t], red[t + s]); __syncthreads(); }
    m = red[0]; __syncthreads();

    float sum = 0.f;
    for (int i = lo + t; i < hi; i += 128) sum += expf(g_gate[i] - m);
    red[t] = sum; __syncthreads();
    #pragma unroll
    for (int s = 64; s; s >>= 1) { if (t < s) red[t] += red[t + s]; __syncthreads(); }
    float denom = red[0]; __syncthreads();
    float inv = (denom > 0.f) ? 1.f / denom : 0.f;

    for (int i = lo + t; i < hi; i += 128) attn_out[i] = expf(g_gate[i] - m) * inv;
    __syncthreads();

    // weighted pool, unrolled x4 for MLP
    float acc = 0.f;
    int i = lo;
    for (; i + 4 <= hi; i += 4) {
        float a0 = attn_out[i],     a1 = attn_out[i + 1];
        float a2 = attn_out[i + 2], a3 = attn_out[i + 3];
        float v0 = g_h1[(size_t)i * D + t];
        float v1 = g_h1[(size_t)(i + 1) * D + t];
        float v2 = g_h1[(size_t)(i + 2) * D + t];
        float v3 = g_h1[(size_t)(i + 3) * D + t];
        acc += a0 * v0 + a1 * v1 + a2 * v2 + a3 * v3;
    }
    for (; i < hi; i++) acc += attn_out[i] * g_h1[(size_t)i * D + t];
    gemb[gidx * D + t] = acc;
}

// ---------------- K8: head, 8 graphs per block ----------------
#define GPG 8
__global__ void __launch_bounds__(128) k_head(const float* __restrict__ text,
                                              const float* __restrict__ featm,
                                              const float* __restrict__ msgW,
                                              const float* __restrict__ msgb,
                                              const float* __restrict__ featW,
                                              const float* __restrict__ featb,
                                              const float* __restrict__ mw,
                                              const float* __restrict__ mb,
                                              const float* __restrict__ fcW,
                                              const float* __restrict__ fcb,
                                              const float* __restrict__ gws,
                                              const float* __restrict__ gemb,
                                              float* __restrict__ logits) {
    __shared__ float ts[GPG][TXT];     // 24 KB
    __shared__ float fs[GPG][MAN];
    __shared__ float red[128];
    int g0 = blockIdx.x * GPG, t = threadIdx.x;

    for (int i = t; i < GPG * TXT; i += 128) {
        int q = i / TXT, k = i % TXT;
        ts[q][k] = text[(size_t)(g0 + q) * TXT + k];
    }
    for (int i = t; i < GPG * MAN; i += 128) {
        int q = i / MAN, k = i % MAN;
        fs[q][k] = featm[(size_t)(g0 + q) * MAN + k];
    }
    __syncthreads();

    float accm[GPG];
    #pragma unroll
    for (int q = 0; q < GPG; q++) accm[q] = 0.f;
    #pragma unroll 4
    for (int k = 0; k < TXT; k++) {
        float w = msgW[(size_t)k * D + t];
        #pragma unroll
        for (int q = 0; q < GPG; q++) accm[q] += ts[q][k] * w;
    }
    float mbv = msgb[t];
    #pragma unroll
    for (int q = 0; q < GPG; q++) accm[q] = gelu_exact(accm[q] + mbv);

    float accf[GPG];
    #pragma unroll
    for (int q = 0; q < GPG; q++) accf[q] = 0.f;
    #pragma unroll
    for (int k = 0; k < MAN; k++) {
        float w = featW[(size_t)k * D + t];
        #pragma unroll
        for (int q = 0; q < GPG; q++) accf[q] += fs[q][k] * w;
    }
    float fbv = featb[t];
    #pragma unroll
    for (int q = 0; q < GPG; q++) accf[q] = gelu_exact(accf[q] + fbv);

    float gwscale = gws[0];
    float mw0 = mw[t], mw1 = mw[D + t], mw2 = mw[2 * D + t];
    float mb0 = mb[t], mb1 = mb[D + t], mb2 = mb[2 * D + t];
    float fw0 = fcW[t], fw1 = fcW[D + t], fw2 = fcW[2 * D + t];
    float fcb0 = fcb[0];

    for (int q = 0; q < GPG; q++) {
        float e0 = gwscale * gemb[(size_t)(g0 + q) * D + t];
        float s = e0 + accm[q] + accf[q];
        red[t] = s; __syncthreads();
        #pragma unroll
        for (int ss = 64; ss; ss >>= 1) { if (t < ss) red[t] += red[t + ss]; __syncthreads(); }
        float mu = red[0] * (1.f / 384.f); __syncthreads();

        float d0 = e0 - mu, d1 = accm[q] - mu, d2 = accf[q] - mu;
        float qq = d0 * d0 + d1 * d1 + d2 * d2;
        red[t] = qq; __syncthreads();
        #pragma unroll
        for (int ss = 64; ss; ss >>= 1) { if (t < ss) red[t] += red[t + ss]; __syncthreads(); }
        float rstd = rsqrtf(red[0] * (1.f / 384.f) + LN_EPS); __syncthreads();

        float n0 = d0 * rstd * mw0 + mb0;
        float n1 = d1 * rstd * mw1 + mb1;
        float n2 = d2 * rstd * mw2 + mb2;
        float p = n0 * fw0 + n1 * fw1 + n2 * fw2;
        red[t] = p; __syncthreads();
        #pragma unroll
        for (int ss = 64; ss; ss >>= 1) { if (t < ss) red[t] += red[t + ss]; __syncthreads(); }
        if (t == 0) logits[g0 + q] = red[0] + fcb0;
        __syncthreads();
    }
}

// ---------------- launch ----------------
extern "C" void kernel_launch(void* const* d_in, const int* in_sizes, int n_in,
                              void* d_out, int out_size) {
    (void)n_in; (void)out_size;
    const float* x          = (const float*)d_in[0];
    const int*   edge_index = (const int*)  d_in[1];
    const int*   batch      = (const int*)  d_in[2];
    int o = (in_sizes[3] == 1) ? 1 : 0;   // skip scalar batch_size slot if present
    const float* text     = (const float*)d_in[3 + o];
    const float* featm    = (const float*)d_in[4 + o];
    const float* ln_pw    = (const float*)d_in[5 + o];
    const float* ln_pb    = (const float*)d_in[6 + o];
    const float* W_l      = (const float*)d_in[7 + o];
    const float* b_l      = (const float*)d_in[8 + o];
    const float* W_r      = (const float*)d_in[9 + o];
    const float* ln_cw    = (const float*)d_in[10 + o];
    const float* ln_cb    = (const float*)d_in[11 + o];
    const float* gate_w   = (const float*)d_in[12 + o];
    const float* gate_b   = (const float*)d_in[13 + o];
    const float* gweight  = (const float*)d_in[14 + o];
    const float* msg_W    = (const float*)d_in[15 + o];
    const float* msg_b    = (const float*)d_in[16 + o];
    const float* feat_W   = (const float*)d_in[17 + o];
    const float* feat_b   = (const float*)d_in[18 + o];
    const float* mixed_w  = (const float*)d_in[19 + o];
    const float* mixed_b  = (const float*)d_in[20 + o];
    const float* fc1_W    = (const float*)d_in[21 + o];
    const float* fc1_b    = (const float*)d_in[22 + o];

    float* out     = (float*)d_out;
    float* logits  = out;                 // [512]
    float* gemb    = out + NG;            // [512,128]
    float* attn    = out + NG + NG * D;   // [50000]

    cudaFuncSetAttribute(k_gemm_fused, cudaFuncAttributeMaxDynamicSharedMemorySize,
                         SM_FLOATS * (int)sizeof(float));

    k_ln_project<<<(N_NODES + 7) / 8, 256>>>(x, ln_pw, ln_pb);
    k_hist<<<(N_EDGES + 255) / 256, 256>>>(edge_index);
    k_scanA<<<SCAN_BLOCKS, 1024>>>();
    k_scanB<<<1, 64>>>();
    k_scanC<<<(N_NODES + 255) / 256, 256>>>();
    k_edge_sort<<<(N_EDGES + 255) / 256, 256>>>(edge_index);
    k_aggregate<<<(N_NODES * 32 + 255) / 256, 256>>>();
    k_gemm_fused<<<(N_NODES + GBM - 1) / GBM, 256, SM_FLOATS * sizeof(float)>>>(
        W_l, W_r, b_l, ln_cw, ln_cb, gate_w, gate_b);
    k_attn_pool<<<NG, 128>>>(batch, attn, gemb);
    k_head<<<NG / GPG, 128>>>(text, featm, msg_W, msg_b, feat_W, feat_b,
                              mixed_w, mixed_b, fc1_W, fc1_b, gweight, gemb, logits);
}